// round 15
// baseline (speedup 1.0000x reference)
#include <cuda_runtime.h>
#include <cuda_fp16.h>
#include <cstdint>
#include <cstddef>

#define BATCH 64
#define T 90
#define O 5
#define D 256
#define H 256
#define EA 4096
#define R 5
#define NB 8
#define NPG 95
#define NTOT (BATCH*NPG)      /* 6080 */
#define JW 1536               /* 5*256 relation cols + 256 root cols */
#define XWC 1280              /* relation part of xW */
#define MROWS 6144            /* NTOT padded to 48*128 */
#define KP 256                /* single fp16 term */
#define KTILES 29             /* ceil(450/16) */

// ---------------- device scratch ----------------
__device__ __align__(128) __half g_xWh[(size_t)NTOT*XWC];         // 15.6 MB fp16
__device__ __align__(128) float g_P[(size_t)BATCH*T*T];           // softmax probs
__device__ __align__(128) __half g_Abf[(size_t)MROWS*KP];         // 3.1 MB  [row][k]
__device__ __align__(128) __half g_Bbf[(size_t)JW*KP];            // 0.8 MB  [n][k]
__device__ __align__(128) __half g_C[(size_t)BATCH*KTILES*96*16]; // 5.7 MB tiled C

// ---------------- PTX helpers (baseline-PTX only: sm_80-class) ----------------
__device__ __forceinline__ uint32_t smem_u32(const void* p) {
    uint32_t a;
    asm("{ .reg .u64 t; cvta.to.shared.u64 t, %1; cvt.u32.u64 %0, t; }" : "=r"(a) : "l"(p));
    return a;
}
#define CP16(dst,src)    asm volatile("cp.async.cg.shared.global [%0], [%1], 16;"::"r"(dst),"l"(src):"memory")
#define CP_COMMIT()      asm volatile("cp.async.commit_group;":::"memory")
#define CP_WAIT(n)       asm volatile("cp.async.wait_group %0;"::"n"(n):"memory")
#define LDSM4(r0,r1,r2,r3,addr) \
    asm volatile("ldmatrix.sync.aligned.m8n8.x4.shared.b16 {%0,%1,%2,%3}, [%4];" \
                 : "=r"(r0),"=r"(r1),"=r"(r2),"=r"(r3) : "r"(addr))
#define LDSM4T(r0,r1,r2,r3,addr) \
    asm volatile("ldmatrix.sync.aligned.m8n8.x4.trans.shared.b16 {%0,%1,%2,%3}, [%4];" \
                 : "=r"(r0),"=r"(r1),"=r"(r2),"=r"(r3) : "r"(addr))
#define MMA16816(c, a, b0, b1) \
    asm volatile("mma.sync.aligned.m16n8k16.row.col.f32.f16.f16.f32 " \
                 "{%0,%1,%2,%3},{%4,%5,%6,%7},{%8,%9},{%0,%1,%2,%3};" \
                 : "+f"((c)[0]),"+f"((c)[1]),"+f"((c)[2]),"+f"((c)[3]) \
                 : "r"((a)[0]),"r"((a)[1]),"r"((a)[2]),"r"((a)[3]),"r"(b0),"r"(b1))

// ---------------- K1: prep = buildB + convA fused -------------------------
#define PREP_B_BLOCKS ((D*JW)/256)          /* 1536 */
#define PREP_A_BLOCKS ((MROWS*256)/256)     /* 6144 */
__global__ void k_prep(const float* __restrict__ bases,
                       const float* __restrict__ comp,
                       const float* __restrict__ root,
                       const float* __restrict__ x) {
    int bid = blockIdx.x, tid = threadIdx.x;
    if (bid < PREP_B_BLOCKS) {
        int idx = bid*256 + tid;
        int d = idx / JW, j = idx - d*JW;
        float v;
        if (j < XWC) {
            int r = j >> 8, h = j & 255;
            float s = 0.f;
            #pragma unroll
            for (int n = 0; n < NB; n++)
                s += comp[r*NB + n] * bases[((size_t)n*D + d)*H + h];
            v = s;
        } else {
            v = root[d*H + (j - XWC)];
        }
        g_Bbf[(size_t)j*KP + d] = __float2half(v);
    } else {
        int idx = (bid - PREP_B_BLOCKS)*256 + tid;
        int row = idx >> 8, col = idx & 255;
        float v = (row < NTOT) ? x[(size_t)row*D + col] : 0.f;
        g_Abf[(size_t)row*KP + col] = __float2half(v);
    }
}

// ---------------- K3: attention, 2 CTAs per graph (column halves) ---------
#define ATTN_SMEM ((96*257 + 48*257 + 90*49)*(int)sizeof(float))  /* 165672 */
__global__ void __launch_bounds__(128) k_attn(const float* __restrict__ M,
                                              const float* __restrict__ Ws) {
    extern __shared__ float sm[];
    float* sM = sm;                        // [96][257]
    float* sW = sm + 96*257;               // [48][257]
    float* sS = sm + 96*257 + 48*257;      // [90][49]
    int b = blockIdx.x >> 1;
    int sh = (blockIdx.x & 1) * 48;
    int tid = threadIdx.x;

    for (int q = tid; q < T*(D/4); q += 128) {
        int m = q >> 6, d4 = (q & 63) << 2;
        float4 v = *(const float4*)(M + ((size_t)b*T + m)*D + d4);
        float* p = sM + m*257 + d4;
        p[0]=v.x; p[1]=v.y; p[2]=v.z; p[3]=v.w;
    }
    for (int q = tid; q < 6*257; q += 128) sM[90*257 + q] = 0.f;
    for (int q = tid; q < 48*(D/4); q += 128) {
        int r = q >> 6, d4 = (q & 63) << 2;
        int s = sh + r;
        float4 v = make_float4(0.f,0.f,0.f,0.f);
        if (s < T) v = *(const float4*)(Ws + (size_t)s*D + d4);
        float* p = sW + r*257 + d4;
        p[0]=v.x; p[1]=v.y; p[2]=v.z; p[3]=v.w;
    }
    __syncthreads();

    int tx = tid & 7, ty = tid >> 3;
    int m0 = ty*6, s0 = tx*6;
    float acc[6][6];
    #pragma unroll
    for (int i = 0; i < 6; i++)
        #pragma unroll
        for (int j = 0; j < 6; j++) acc[i][j] = 0.f;
    for (int k = 0; k < D; k++) {
        float a[6], bb[6];
        #pragma unroll
        for (int i = 0; i < 6; i++) { a[i] = sM[(m0+i)*257 + k]; bb[i] = sW[(s0+i)*257 + k]; }
        #pragma unroll
        for (int i = 0; i < 6; i++)
            #pragma unroll
            for (int j = 0; j < 6; j++) acc[i][j] += a[i]*bb[j];
    }
    #pragma unroll
    for (int i = 0; i < 6; i++)
        #pragma unroll
        for (int j = 0; j < 6; j++) {
            int m = m0+i, sl = s0+j;
            if (m < T && sh + sl < T) sS[m*49 + sl] = acc[i][j];
        }
    __syncthreads();

    if (tid < 48 && sh + tid < T) {
        int sl = tid, sg = sh + tid;
        float mx = -1e30f;
        for (int t = 0; t < T; t++) mx = fmaxf(mx, sS[t*49 + sl]);
        float den = 0.f;
        for (int t = 0; t < T; t++) den += __expf(sS[t*49 + sl] - mx);
        float inv = 1.f/den;
        for (int t = 0; t < T; t++)
            g_P[((size_t)b*T + t)*T + sg] = __expf(sS[t*49 + sl] - mx) * inv;
    }
}

// ---------------- K4: scatter — P staged in smem, fp32 C, fp16 writeout ---
#define CFP 464               /* fp32 C pitch = 29*16, exactly the ktile grid */
#define SCAT_SMEM (96*CFP*4 + T*T*4)   /* 178176 + 32400 = 210576 */
__global__ void __launch_bounds__(256) k_scatter(const int* __restrict__ edge_src,
                                                 const int* __restrict__ edge_dst,
                                                 const int* __restrict__ edge_type,
                                                 const float* __restrict__ node_att) {
    extern __shared__ float smc[];
    float* Cf = smc;                 // [96][CFP]
    float* sP = smc + 96*CFP;        // [T*T] flat
    int b = blockIdx.x, tid = threadIdx.x;

    // stage P[b] (32.4 KB, coalesced) + zero C
    const float4* gp = (const float4*)(g_P + (size_t)b*T*T);
    for (int i = tid; i < (T*T)/4; i += 256) ((float4*)sP)[i] = gp[i];
    float4 z4 = make_float4(0.f,0.f,0.f,0.f);
    for (int i = tid; i < 96*CFP/4; i += 256) ((float4*)Cf)[i] = z4;
    __syncthreads();

    // scatter: native fp32 smem atomics, P reads from smem (~29 cyc)
    #pragma unroll
    for (int q = 0; q < EA/256; q++) {
        int e = tid + q*256;
        int src = edge_src[(size_t)b*EA + e];
        int dst = edge_dst[(size_t)b*EA + e];
        int ty  = edge_type[(size_t)b*EA + e];
        atomicAdd(&Cf[dst*CFP + src*R + ty], sP[dst*T + src]);
    }
    // tag entries (rows 90..94, unique addresses)
    for (int q = tid; q < T*O; q += 256) {
        int src = q / O, o = q - src*O;
        Cf[(T+o)*CFP + src*R + (R-1)] = node_att[((size_t)b*T + src)*O + o];
    }
    __syncthreads();

    // writeout: convert fp32 -> fp16, tiled g_C[b][kt][row][16]
    for (int i = tid; i < KTILES*96; i += 256) {
        int kt = i / 96, row = i - kt*96;
        const float* src = Cf + row*CFP + kt*16;
        uint32_t h[8];
        #pragma unroll
        for (int j = 0; j < 8; j++) {
            __half2 hv = __floats2half2_rn(src[2*j], src[2*j+1]);
            h[j] = *(uint32_t*)&hv;
        }
        __half* dst = g_C + (((size_t)b*KTILES + kt)*96 + row)*16;
        *(uint4*)dst       = make_uint4(h[0], h[1], h[2], h[3]);
        *(uint4*)(dst + 8) = make_uint4(h[4], h[5], h[6], h[7]);
    }
}

// ---------------- K2: mma.sync fp16 GEMM, 4-stage pipeline ----------------
#define SPITCH 40
#define STAGE_HALVES (128*SPITCH)
#define NKT (KP/32)          /* 8 */
#define NSTAGE 4
#define MM_SMEM (2*NSTAGE*STAGE_HALVES*2)   /* 81920 B */

__global__ void __launch_bounds__(256, 2) k_mm(const float* __restrict__ bias,
                                               float* __restrict__ out) {
    extern __shared__ __half smm[];
    uint32_t sbA = smem_u32(smm);
    uint32_t sbB = sbA + NSTAGE*STAGE_HALVES*2;
    int tid = threadIdx.x, lane = tid & 31, wid = tid >> 5;
    int warpM = wid & 3, warpN = wid >> 2;
    int row0 = blockIdx.x * 128;
    int colTile = blockIdx.y, col0 = colTile * 128;

    float c[2][8][4];
    #pragma unroll
    for (int mt = 0; mt < 2; mt++)
        #pragma unroll
        for (int nt = 0; nt < 8; nt++)
            #pragma unroll
            for (int q = 0; q < 4; q++) c[mt][nt][q] = 0.f;

    int lrow = tid >> 2, lseg = tid & 3;
    const __half* gA = g_Abf + (size_t)(row0 + lrow)*KP + lseg*8;
    const __half* gB = g_Bbf + (size_t)(col0 + lrow)*KP + lseg*8;
    uint32_t dA = sbA + (lrow*SPITCH + lseg*8)*2;
    uint32_t dB = sbB + (lrow*SPITCH + lseg*8)*2;
    const int rstep = 64;

    #pragma unroll
    for (int p = 0; p < NSTAGE-1; p++) {
        size_t go = (size_t)p*32;
        uint32_t soff = p * STAGE_HALVES * 2;
        CP16(dA + soff,                  (const char*)(gA + go));
        CP16(dA + soff + rstep*SPITCH*2, (const char*)(gA + go + (size_t)rstep*KP));
        CP16(dB + soff,                  (const char*)(gB + go));
        CP16(dB + soff + rstep*SPITCH*2, (const char*)(gB + go + (size_t)rstep*KP));
        CP_COMMIT();
    }

    int aRow = warpM*32 + ((lane>>3)&1)*8 + (lane&7);
    int aCol = ((lane>>4)&1)*8;
    int bRow = warpN*64 + ((lane>>4)&1)*8 + (lane&7);
    int bCol = ((lane>>3)&1)*8;
    uint32_t aAddr0 = sbA + (aRow*SPITCH + aCol)*2;
    uint32_t bAddr0 = sbB + (bRow*SPITCH + bCol)*2;

    #pragma unroll
    for (int kt = 0; kt < NKT; kt++) {
        if (kt <= NKT-3)      { CP_WAIT(2); }
        else if (kt == NKT-2) { CP_WAIT(1); }
        else                  { CP_WAIT(0); }
        __syncthreads();

        if (kt + NSTAGE - 1 < NKT) {
            size_t go = (size_t)(kt + NSTAGE - 1)*32;
            uint32_t soff = ((kt + NSTAGE - 1) & (NSTAGE-1)) * STAGE_HALVES * 2;
            CP16(dA + soff,                  (const char*)(gA + go));
            CP16(dA + soff + rstep*SPITCH*2, (const char*)(gA + go + (size_t)rstep*KP));
            CP16(dB + soff,                  (const char*)(gB + go));
            CP16(dB + soff + rstep*SPITCH*2, (const char*)(gB + go + (size_t)rstep*KP));
            CP_COMMIT();
        }

        uint32_t sa  = aAddr0 + (kt & (NSTAGE-1)) * STAGE_HALVES * 2;
        uint32_t sb2 = bAddr0 + (kt & (NSTAGE-1)) * STAGE_HALVES * 2;
        #pragma unroll
        for (int ks = 0; ks < 2; ks++) {
            uint32_t a[2][4];
            LDSM4(a[0][0],a[0][1],a[0][2],a[0][3], sa + ks*32);
            LDSM4(a[1][0],a[1][1],a[1][2],a[1][3], sa + ks*32 + 16*SPITCH*2);
            uint32_t b[8][2];
            #pragma unroll
            for (int ntp = 0; ntp < 4; ntp++) {
                uint32_t r0,r1,r2,r3;
                LDSM4(r0,r1,r2,r3, sb2 + ks*32 + ntp*16*SPITCH*2);
                b[ntp*2+0][0]=r0; b[ntp*2+0][1]=r1;
                b[ntp*2+1][0]=r2; b[ntp*2+1][1]=r3;
            }
            #pragma unroll
            for (int mt = 0; mt < 2; mt++)
                #pragma unroll
                for (int nt = 0; nt < 8; nt++)
                    MMA16816(c[mt][nt], a[mt], b[nt][0], b[nt][1]);
        }
    }

    int gr = lane >> 2, ci = lane & 3;
    #pragma unroll
    for (int mt = 0; mt < 2; mt++) {
        int r0w = row0 + warpM*32 + mt*16 + gr;
        #pragma unroll
        for (int nt = 0; nt < 8; nt++) {
            int col = col0 + warpN*64 + nt*8 + ci*2;
            if (colTile < 10) {
                if (r0w < NTOT)
                    *(__half2*)(g_xWh + (size_t)r0w*XWC + col) =
                        __floats2half2_rn(c[mt][nt][0], c[mt][nt][1]);
                if (r0w + 8 < NTOT)
                    *(__half2*)(g_xWh + (size_t)(r0w+8)*XWC + col) =
                        __floats2half2_rn(c[mt][nt][2], c[mt][nt][3]);
            } else {
                int h = col - XWC;
                float b0 = bias[h], b1 = bias[h+1];
                if (r0w < NTOT)
                    *(float2*)(out + (size_t)r0w*H + h) = make_float2(c[mt][nt][0] + b0, c[mt][nt][1] + b1);
                if (r0w + 8 < NTOT)
                    *(float2*)(out + (size_t)(r0w+8)*H + h) = make_float2(c[mt][nt][2] + b0, c[mt][nt][3] + b1);
            }
        }
    }
}

// ---------------- K5: dense edge GEMM, C from global, 4-stage -------------
#define C2PITCH 24           /* 48 B row pitch for C tile (conflict-free) */
#define BPITCH 136
#define NBST 4
#define CSTG (96*C2PITCH*2)              /* 4608 */
#define BSTG (16*BPITCH*2)               /* 4352 */
#define STG  (CSTG + BSTG)               /* 8960 */
#define AGG_SMEM (NBST*STG)              /* 35840 */

__global__ void __launch_bounds__(256) k_agg2(float* __restrict__ out) {
    extern __shared__ __half sm2[];
    uint32_t sb = smem_u32(sm2);
    int b = blockIdx.x >> 1, nh = blockIdx.x & 1;
    int tid = threadIdx.x, lane = tid & 31, w = tid >> 5;
    int n0 = nh * 128;

    int lrow = tid >> 4, lch = tid & 15;                 // B: 16 rows x 16 chunks
    int crow = tid >> 1, cc = tid & 1;                   // C: 96 rows x 2 chunks (tid<192)

    #pragma unroll
    for (int p = 0; p < NBST-1; p++) {
        int kt = p;
        {
            int k = kt*16 + lrow;
            int src = k / R, ty = k - src*R;
            const __half* sp = g_xWh + ((size_t)(b*NPG + src)*XWC + ty*H + n0) + lch*8;
            CP16(sb + p*STG + CSTG + lrow*(BPITCH*2) + lch*16, (const char*)sp);
        }
        if (tid < 192) {
            const __half* sp = g_C + (((size_t)b*KTILES + kt)*96 + crow)*16 + cc*8;
            CP16(sb + p*STG + crow*(C2PITCH*2) + cc*16, (const char*)sp);
        }
        CP_COMMIT();
    }

    float acc[6][2][4];
    #pragma unroll
    for (int mt = 0; mt < 6; mt++)
        #pragma unroll
        for (int nt = 0; nt < 2; nt++)
            #pragma unroll
            for (int q = 0; q < 4; q++) acc[mt][nt][q] = 0.f;

    uint32_t aOff = ((((lane>>3)&1)*8 + (lane&7))*C2PITCH + ((lane>>4)&1)*8)*2;
    uint32_t bOff = CSTG + (((lane>>3)&1)*8 + (lane&7))*(BPITCH*2) + (w*16 + ((lane>>4)&1)*8)*2;

    for (int kt = 0; kt < KTILES; kt++) {
        if (kt < KTILES-2)       { CP_WAIT(2); }
        else if (kt == KTILES-2) { CP_WAIT(1); }
        else                     { CP_WAIT(0); }
        __syncthreads();

        if (kt + NBST - 1 < KTILES) {
            int kp = kt + NBST - 1;
            int sidx = kp & (NBST-1);
            {
                int k = kp*16 + lrow;
                int src = k / R, ty = k - src*R;
                const __half* sp = g_xWh + ((size_t)(b*NPG + src)*XWC + ty*H + n0) + lch*8;
                CP16(sb + sidx*STG + CSTG + lrow*(BPITCH*2) + lch*16, (const char*)sp);
            }
            if (tid < 192) {
                const __half* sp = g_C + (((size_t)b*KTILES + kp)*96 + crow)*16 + cc*8;
                CP16(sb + sidx*STG + crow*(C2PITCH*2) + cc*16, (const char*)sp);
            }
            CP_COMMIT();
        }

        uint32_t stg = sb + (kt & (NBST-1))*STG;
        uint32_t bb0, bb1, bb2, bb3;
        LDSM4T(bb0, bb1, bb2, bb3, stg + bOff);
        #pragma unroll
        for (int mt = 0; mt < 6; mt++) {
            uint32_t a[4];
            LDSM4(a[0], a[1], a[2], a[3], stg + aOff + mt*16*C2PITCH*2);
            MMA16816(acc[mt][0], a, bb0, bb1);
            MMA16816(acc[mt][1], a, bb2, bb3);
        }
    }

    int gr = lane >> 2, ci = lane & 3;
    #pragma unroll
    for (int mt = 0; mt < 6; mt++) {
        #pragma unroll
        for (int hrow = 0; hrow < 2; hrow++) {
            int row = mt*16 + gr + hrow*8;
            if (row < NPG) {
                size_t node = (size_t)b*NPG + row;
                #pragma unroll
                for (int nt = 0; nt < 2; nt++) {
                    int col = n0 + w*16 + nt*8 + ci*2;
                    float2* p = (float2*)(out + node*H + col);
                    float2 v = *p;
                    v.x += acc[mt][nt][hrow*2 + 0];
                    v.y += acc[mt][nt][hrow*2 + 1];
                    *p = v;
                }
            }
        }
    }
}

// ---------------- launch (fork-join graph concurrency) --------------------
extern "C" void kernel_launch(void* const* d_in, const int* in_sizes, int n_in,
                              void* d_out, int out_size) {
    const float* M     = (const float*)d_in[0];
    const float* x     = (const float*)d_in[1];
    const float* natt  = (const float*)d_in[2];
    const float* Ws    = (const float*)d_in[3];
    const float* bases = (const float*)d_in[4];
    const float* comp  = (const float*)d_in[5];
    const float* root  = (const float*)d_in[6];
    const float* bias  = (const float*)d_in[7];
    const int* esrc    = (const int*)d_in[8];
    const int* edst    = (const int*)d_in[9];
    const int* etyp    = (const int*)d_in[10];
    float* out = (float*)d_out;

    static cudaStream_t s1 = nullptr;
    static cudaEvent_t  ef = nullptr, e1 = nullptr;
    static bool attr_done = false;
    if (!s1) {
        cudaStreamCreateWithFlags(&s1, cudaStreamNonBlocking);
        cudaEventCreateWithFlags(&ef, cudaEventDisableTiming);
        cudaEventCreateWithFlags(&e1, cudaEventDisableTiming);
    }
    if (!attr_done) {
        cudaFuncSetAttribute(k_attn,    cudaFuncAttributeMaxDynamicSharedMemorySize, ATTN_SMEM);
        cudaFuncSetAttribute(k_scatter, cudaFuncAttributeMaxDynamicSharedMemorySize, SCAT_SMEM);
        cudaFuncSetAttribute(k_agg2,    cudaFuncAttributeMaxDynamicSharedMemorySize, AGG_SMEM);
        cudaFuncSetAttribute(k_mm,      cudaFuncAttributeMaxDynamicSharedMemorySize, MM_SMEM);
        attr_done = true;
    }

    // fork attn+scatter onto s1 (independent of the GEMM chain)
    cudaEventRecord(ef, 0);
    cudaStreamWaitEvent(s1, ef, 0);
    k_attn<<<2*BATCH, 128, ATTN_SMEM, s1>>>(M, Ws);
    k_scatter<<<BATCH, 256, SCAT_SMEM, s1>>>(esrc, edst, etyp, natt);

    // main chain: prep -> mm
    k_prep<<<PREP_B_BLOCKS + PREP_A_BLOCKS, 256>>>(bases, comp, root, x);
    k_mm<<<dim3(MROWS/128, JW/128), 256, MM_SMEM>>>(bias, out);

    // join scatter before agg2
    cudaEventRecord(e1, s1);
    cudaStreamWaitEvent(0, e1, 0);
    k_agg2<<<2*BATCH, 256, AGG_SMEM>>>(out);
}

// round 16
// speedup vs baseline: 1.0514x; 1.0514x over previous
#include <cuda_runtime.h>
#include <cuda_fp16.h>
#include <cstdint>
#include <cstddef>

#define BATCH 64
#define T 90
#define O 5
#define D 256
#define H 256
#define EA 4096
#define R 5
#define NB 8
#define NPG 95
#define NTOT (BATCH*NPG)      /* 6080 */
#define JW 1536               /* 5*256 relation cols + 256 root cols */
#define XWC 1280              /* relation part of xW */
#define MROWS 6144            /* NTOT padded to 48*128 */
#define KP 256                /* single fp16 term */
#define KTILES 29             /* ceil(450/16) */

// ---------------- device scratch ----------------
__device__ __align__(128) __half g_xWh[(size_t)NTOT*XWC];         // 15.6 MB fp16
__device__ __align__(128) float g_P[(size_t)BATCH*T*T];           // softmax probs
__device__ __align__(128) __half g_Abf[(size_t)MROWS*KP];         // 3.1 MB  [row][k]
__device__ __align__(128) __half g_Bbf[(size_t)JW*KP];            // 0.8 MB  [n][k]

// ---------------- PTX helpers (baseline-PTX only: sm_80-class) ----------------
__device__ __forceinline__ uint32_t smem_u32(const void* p) {
    uint32_t a;
    asm("{ .reg .u64 t; cvta.to.shared.u64 t, %1; cvt.u32.u64 %0, t; }" : "=r"(a) : "l"(p));
    return a;
}
#define CP16(dst,src)    asm volatile("cp.async.cg.shared.global [%0], [%1], 16;"::"r"(dst),"l"(src):"memory")
#define CP_COMMIT()      asm volatile("cp.async.commit_group;":::"memory")
#define CP_WAIT(n)       asm volatile("cp.async.wait_group %0;"::"n"(n):"memory")
#define LDSM4(r0,r1,r2,r3,addr) \
    asm volatile("ldmatrix.sync.aligned.m8n8.x4.shared.b16 {%0,%1,%2,%3}, [%4];" \
                 : "=r"(r0),"=r"(r1),"=r"(r2),"=r"(r3) : "r"(addr))
#define LDSM4T(r0,r1,r2,r3,addr) \
    asm volatile("ldmatrix.sync.aligned.m8n8.x4.trans.shared.b16 {%0,%1,%2,%3}, [%4];" \
                 : "=r"(r0),"=r"(r1),"=r"(r2),"=r"(r3) : "r"(addr))
#define MMA16816(c, a, b0, b1) \
    asm volatile("mma.sync.aligned.m16n8k16.row.col.f32.f16.f16.f32 " \
                 "{%0,%1,%2,%3},{%4,%5,%6,%7},{%8,%9},{%0,%1,%2,%3};" \
                 : "+f"((c)[0]),"+f"((c)[1]),"+f"((c)[2]),"+f"((c)[3]) \
                 : "r"((a)[0]),"r"((a)[1]),"r"((a)[2]),"r"((a)[3]),"r"(b0),"r"(b1))

// ---------------- K1: prep = buildB + convA fused -------------------------
#define PREP_B_BLOCKS ((D*JW)/256)          /* 1536 */
#define PREP_A_BLOCKS ((MROWS*256)/256)     /* 6144 */
__global__ void k_prep(const float* __restrict__ bases,
                       const float* __restrict__ comp,
                       const float* __restrict__ root,
                       const float* __restrict__ x) {
    int bid = blockIdx.x, tid = threadIdx.x;
    if (bid < PREP_B_BLOCKS) {
        int idx = bid*256 + tid;
        int d = idx / JW, j = idx - d*JW;
        float v;
        if (j < XWC) {
            int r = j >> 8, h = j & 255;
            float s = 0.f;
            #pragma unroll
            for (int n = 0; n < NB; n++)
                s += comp[r*NB + n] * bases[((size_t)n*D + d)*H + h];
            v = s;
        } else {
            v = root[d*H + (j - XWC)];
        }
        g_Bbf[(size_t)j*KP + d] = __float2half(v);
    } else {
        int idx = (bid - PREP_B_BLOCKS)*256 + tid;
        int row = idx >> 8, col = idx & 255;
        float v = (row < NTOT) ? x[(size_t)row*D + col] : 0.f;
        g_Abf[(size_t)row*KP + col] = __float2half(v);
    }
}

// ---------------- K3: attention, 2 CTAs per graph (column halves) ---------
#define ATTN_SMEM ((96*257 + 48*257 + 90*49)*(int)sizeof(float))  /* 165672 */
__global__ void __launch_bounds__(128) k_attn(const float* __restrict__ M,
                                              const float* __restrict__ Ws) {
    extern __shared__ float sm[];
    float* sM = sm;                        // [96][257]
    float* sW = sm + 96*257;               // [48][257]
    float* sS = sm + 96*257 + 48*257;      // [90][49]
    int b = blockIdx.x >> 1;
    int sh = (blockIdx.x & 1) * 48;
    int tid = threadIdx.x;

    for (int q = tid; q < T*(D/4); q += 128) {
        int m = q >> 6, d4 = (q & 63) << 2;
        float4 v = *(const float4*)(M + ((size_t)b*T + m)*D + d4);
        float* p = sM + m*257 + d4;
        p[0]=v.x; p[1]=v.y; p[2]=v.z; p[3]=v.w;
    }
    for (int q = tid; q < 6*257; q += 128) sM[90*257 + q] = 0.f;
    for (int q = tid; q < 48*(D/4); q += 128) {
        int r = q >> 6, d4 = (q & 63) << 2;
        int s = sh + r;
        float4 v = make_float4(0.f,0.f,0.f,0.f);
        if (s < T) v = *(const float4*)(Ws + (size_t)s*D + d4);
        float* p = sW + r*257 + d4;
        p[0]=v.x; p[1]=v.y; p[2]=v.z; p[3]=v.w;
    }
    __syncthreads();

    int tx = tid & 7, ty = tid >> 3;
    int m0 = ty*6, s0 = tx*6;
    float acc[6][6];
    #pragma unroll
    for (int i = 0; i < 6; i++)
        #pragma unroll
        for (int j = 0; j < 6; j++) acc[i][j] = 0.f;
    for (int k = 0; k < D; k++) {
        float a[6], bb[6];
        #pragma unroll
        for (int i = 0; i < 6; i++) { a[i] = sM[(m0+i)*257 + k]; bb[i] = sW[(s0+i)*257 + k]; }
        #pragma unroll
        for (int i = 0; i < 6; i++)
            #pragma unroll
            for (int j = 0; j < 6; j++) acc[i][j] += a[i]*bb[j];
    }
    #pragma unroll
    for (int i = 0; i < 6; i++)
        #pragma unroll
        for (int j = 0; j < 6; j++) {
            int m = m0+i, sl = s0+j;
            if (m < T && sh + sl < T) sS[m*49 + sl] = acc[i][j];
        }
    __syncthreads();

    if (tid < 48 && sh + tid < T) {
        int sl = tid, sg = sh + tid;
        float mx = -1e30f;
        for (int t = 0; t < T; t++) mx = fmaxf(mx, sS[t*49 + sl]);
        float den = 0.f;
        for (int t = 0; t < T; t++) den += __expf(sS[t*49 + sl] - mx);
        float inv = 1.f/den;
        for (int t = 0; t < T; t++)
            g_P[((size_t)b*T + t)*T + sg] = __expf(sS[t*49 + sl] - mx) * inv;
    }
}

// ---------------- K2: mma.sync fp16 GEMM, 4-stage pipeline ----------------
#define SPITCH 40
#define STAGE_HALVES (128*SPITCH)
#define NKT (KP/32)          /* 8 */
#define NSTAGE 4
#define MM_SMEM (2*NSTAGE*STAGE_HALVES*2)   /* 81920 B */

__global__ void __launch_bounds__(256, 2) k_mm(const float* __restrict__ bias,
                                               float* __restrict__ out) {
    extern __shared__ __half smm[];
    uint32_t sbA = smem_u32(smm);
    uint32_t sbB = sbA + NSTAGE*STAGE_HALVES*2;
    int tid = threadIdx.x, lane = tid & 31, wid = tid >> 5;
    int warpM = wid & 3, warpN = wid >> 2;
    int row0 = blockIdx.x * 128;
    int colTile = blockIdx.y, col0 = colTile * 128;

    float c[2][8][4];
    #pragma unroll
    for (int mt = 0; mt < 2; mt++)
        #pragma unroll
        for (int nt = 0; nt < 8; nt++)
            #pragma unroll
            for (int q = 0; q < 4; q++) c[mt][nt][q] = 0.f;

    int lrow = tid >> 2, lseg = tid & 3;
    const __half* gA = g_Abf + (size_t)(row0 + lrow)*KP + lseg*8;
    const __half* gB = g_Bbf + (size_t)(col0 + lrow)*KP + lseg*8;
    uint32_t dA = sbA + (lrow*SPITCH + lseg*8)*2;
    uint32_t dB = sbB + (lrow*SPITCH + lseg*8)*2;
    const int rstep = 64;

    #pragma unroll
    for (int p = 0; p < NSTAGE-1; p++) {
        size_t go = (size_t)p*32;
        uint32_t soff = p * STAGE_HALVES * 2;
        CP16(dA + soff,                  (const char*)(gA + go));
        CP16(dA + soff + rstep*SPITCH*2, (const char*)(gA + go + (size_t)rstep*KP));
        CP16(dB + soff,                  (const char*)(gB + go));
        CP16(dB + soff + rstep*SPITCH*2, (const char*)(gB + go + (size_t)rstep*KP));
        CP_COMMIT();
    }

    int aRow = warpM*32 + ((lane>>3)&1)*8 + (lane&7);
    int aCol = ((lane>>4)&1)*8;
    int bRow = warpN*64 + ((lane>>4)&1)*8 + (lane&7);
    int bCol = ((lane>>3)&1)*8;
    uint32_t aAddr0 = sbA + (aRow*SPITCH + aCol)*2;
    uint32_t bAddr0 = sbB + (bRow*SPITCH + bCol)*2;

    #pragma unroll
    for (int kt = 0; kt < NKT; kt++) {
        if (kt <= NKT-3)      { CP_WAIT(2); }
        else if (kt == NKT-2) { CP_WAIT(1); }
        else                  { CP_WAIT(0); }
        __syncthreads();

        if (kt + NSTAGE - 1 < NKT) {
            size_t go = (size_t)(kt + NSTAGE - 1)*32;
            uint32_t soff = ((kt + NSTAGE - 1) & (NSTAGE-1)) * STAGE_HALVES * 2;
            CP16(dA + soff,                  (const char*)(gA + go));
            CP16(dA + soff + rstep*SPITCH*2, (const char*)(gA + go + (size_t)rstep*KP));
            CP16(dB + soff,                  (const char*)(gB + go));
            CP16(dB + soff + rstep*SPITCH*2, (const char*)(gB + go + (size_t)rstep*KP));
            CP_COMMIT();
        }

        uint32_t sa  = aAddr0 + (kt & (NSTAGE-1)) * STAGE_HALVES * 2;
        uint32_t sb2 = bAddr0 + (kt & (NSTAGE-1)) * STAGE_HALVES * 2;
        #pragma unroll
        for (int ks = 0; ks < 2; ks++) {
            uint32_t a[2][4];
            LDSM4(a[0][0],a[0][1],a[0][2],a[0][3], sa + ks*32);
            LDSM4(a[1][0],a[1][1],a[1][2],a[1][3], sa + ks*32 + 16*SPITCH*2);
            uint32_t b[8][2];
            #pragma unroll
            for (int ntp = 0; ntp < 4; ntp++) {
                uint32_t r0,r1,r2,r3;
                LDSM4(r0,r1,r2,r3, sb2 + ks*32 + ntp*16*SPITCH*2);
                b[ntp*2+0][0]=r0; b[ntp*2+0][1]=r1;
                b[ntp*2+1][0]=r2; b[ntp*2+1][1]=r3;
            }
            #pragma unroll
            for (int mt = 0; mt < 2; mt++)
                #pragma unroll
                for (int nt = 0; nt < 8; nt++)
                    MMA16816(c[mt][nt], a[mt], b[nt][0], b[nt][1]);
        }
    }

    int gr = lane >> 2, ci = lane & 3;
    #pragma unroll
    for (int mt = 0; mt < 2; mt++) {
        int r0w = row0 + warpM*32 + mt*16 + gr;
        #pragma unroll
        for (int nt = 0; nt < 8; nt++) {
            int col = col0 + warpN*64 + nt*8 + ci*2;
            if (colTile < 10) {
                if (r0w < NTOT)
                    *(__half2*)(g_xWh + (size_t)r0w*XWC + col) =
                        __floats2half2_rn(c[mt][nt][0], c[mt][nt][1]);
                if (r0w + 8 < NTOT)
                    *(__half2*)(g_xWh + (size_t)(r0w+8)*XWC + col) =
                        __floats2half2_rn(c[mt][nt][2], c[mt][nt][3]);
            } else {
                int h = col - XWC;
                float b0 = bias[h], b1 = bias[h+1];
                if (r0w < NTOT)
                    *(float2*)(out + (size_t)r0w*H + h) = make_float2(c[mt][nt][0] + b0, c[mt][nt][1] + b1);
                if (r0w + 8 < NTOT)
                    *(float2*)(out + (size_t)(r0w+8)*H + h) = make_float2(c[mt][nt][2] + b0, c[mt][nt][3] + b1);
            }
        }
    }
}

// ---------------- K5: fused edge GEMM, P staged in smem, 4-stage B --------
#define CPITCH 472
#define BPITCH 136
#define NBST 4
#define BSTAGE (16*BPITCH*2)                 /* 4352 B per stage */
#define AGG_SMEM (96*CPITCH*2 + NBST*BSTAGE + T*T*4) /* 90624+17408+32400 = 140432 */

__global__ void __launch_bounds__(256, 1) k_agg2(const int* __restrict__ edge_src,
                                                 const int* __restrict__ edge_dst,
                                                 const int* __restrict__ edge_type,
                                                 const float* __restrict__ node_att,
                                                 float* __restrict__ out) {
    extern __shared__ __half sm2[];
    __half* Cm = sm2;
    uint32_t sbC = smem_u32(Cm);
    uint32_t sbB = sbC + 96*CPITCH*2;
    float* sP = (float*)(sm2 + 96*CPITCH + NBST*16*BPITCH);   // after C + B stages
    int b = blockIdx.x >> 1, nh = blockIdx.x & 1;
    int tid = threadIdx.x, lane = tid & 31, w = tid >> 5;
    int n0 = nh * 128;

    // B loader layout
    int lrow = tid >> 4, lch = tid & 15;
    uint32_t dBs = sbB + lrow*(BPITCH*2) + lch*16;

    // issue B prologue FIRST (stages 0..2) — latency hides under P-stage/zero/scatter
    #pragma unroll
    for (int p = 0; p < NBST-1; p++) {
        int k = p*16 + lrow;
        int src = k / R, ty = k - src*R;
        const __half* sp = g_xWh + ((size_t)(b*NPG + src)*XWC + ty*H + n0) + lch*8;
        CP16(dBs + p*BSTAGE, (const char*)sp);
        CP_COMMIT();
    }

    // stage P[b] into smem (coalesced) and zero C
    const float4* gp = (const float4*)(g_P + (size_t)b*T*T);
    for (int i = tid; i < (T*T)/4; i += 256) ((float4*)sP)[i] = gp[i];
    uint4 z = make_uint4(0,0,0,0);
    for (int i = tid; i < 96*CPITCH/8; i += 256) ((uint4*)Cm)[i] = z;
    __syncthreads();

    // scatter attention edges: C[dst][src*R+ty] += P[dst][src]  (P from smem)
    #pragma unroll
    for (int q = 0; q < EA/256; q++) {
        int e = tid + q*256;
        int src = edge_src[(size_t)b*EA + e];
        int dst = edge_dst[(size_t)b*EA + e];
        int ty  = edge_type[(size_t)b*EA + e];
        atomicAdd(&Cm[dst*CPITCH + src*R + ty], __float2half(sP[dst*T + src]));
    }
    // tag entries (rows 90..94, unique)
    for (int q = tid; q < T*O; q += 256) {
        int src = q / O, o = q - src*O;
        Cm[(T+o)*CPITCH + src*R + (R-1)] = __float2half(node_att[((size_t)b*T + src)*O + o]);
    }

    float acc[6][2][4];
    #pragma unroll
    for (int mt = 0; mt < 6; mt++)
        #pragma unroll
        for (int nt = 0; nt < 2; nt++)
            #pragma unroll
            for (int q = 0; q < 4; q++) acc[mt][nt][q] = 0.f;

    uint32_t aAddr = sbC + ((((lane>>3)&1)*8 + (lane&7))*CPITCH + ((lane>>4)&1)*8)*2;
    uint32_t bAddr = (((lane>>3)&1)*8 + (lane&7))*(BPITCH*2) + (w*16 + ((lane>>4)&1)*8)*2;

    for (int kt = 0; kt < KTILES; kt++) {
        if (kt < KTILES-2)       { CP_WAIT(2); }
        else if (kt == KTILES-2) { CP_WAIT(1); }
        else                     { CP_WAIT(0); }
        __syncthreads();   // stage kt visible; scatter (kt=0) / stage reuse ordered

        if (kt + NBST - 1 < KTILES) {     // prefetch ktile kt+3 into stage (kt+3)&3
            int k = (kt + NBST - 1)*16 + lrow;
            int src = k / R, ty = k - src*R;
            const __half* sp = g_xWh + ((size_t)(b*NPG + src)*XWC + ty*H + n0) + lch*8;
            CP16(dBs + ((kt + NBST - 1) & (NBST-1))*BSTAGE, (const char*)sp);
            CP_COMMIT();
        }

        uint32_t bb0, bb1, bb2, bb3;
        LDSM4T(bb0, bb1, bb2, bb3, sbB + (kt & (NBST-1))*BSTAGE + bAddr);
        #pragma unroll
        for (int mt = 0; mt < 6; mt++) {
            uint32_t a[4];
            LDSM4(a[0], a[1], a[2], a[3], aAddr + mt*16*CPITCH*2 + kt*32);
            MMA16816(acc[mt][0], a, bb0, bb1);
            MMA16816(acc[mt][1], a, bb2, bb3);
        }
        // no trailing sync (4 stages; stage (kt+3)&3 consumed before this barrier)
    }

    int gr = lane >> 2, ci = lane & 3;
    #pragma unroll
    for (int mt = 0; mt < 6; mt++) {
        #pragma unroll
        for (int hrow = 0; hrow < 2; hrow++) {
            int row = mt*16 + gr + hrow*8;
            if (row < NPG) {
                size_t node = (size_t)b*NPG + row;
                #pragma unroll
                for (int nt = 0; nt < 2; nt++) {
                    int col = n0 + w*16 + nt*8 + ci*2;
                    float2* p = (float2*)(out + node*H + col);
                    float2 v = *p;
                    v.x += acc[mt][nt][hrow*2 + 0];
                    v.y += acc[mt][nt][hrow*2 + 1];
                    *p = v;
                }
            }
        }
    }
}

// ---------------- launch (fork-join graph concurrency) --------------------
extern "C" void kernel_launch(void* const* d_in, const int* in_sizes, int n_in,
                              void* d_out, int out_size) {
    const float* M     = (const float*)d_in[0];
    const float* x     = (const float*)d_in[1];
    const float* natt  = (const float*)d_in[2];
    const float* Ws    = (const float*)d_in[3];
    const float* bases = (const float*)d_in[4];
    const float* comp  = (const float*)d_in[5];
    const float* root  = (const float*)d_in[6];
    const float* bias  = (const float*)d_in[7];
    const int* esrc    = (const int*)d_in[8];
    const int* edst    = (const int*)d_in[9];
    const int* etyp    = (const int*)d_in[10];
    float* out = (float*)d_out;

    static cudaStream_t s1 = nullptr;
    static cudaEvent_t  ef = nullptr, e1 = nullptr;
    static bool attr_done = false;
    if (!s1) {
        cudaStreamCreateWithFlags(&s1, cudaStreamNonBlocking);
        cudaEventCreateWithFlags(&ef, cudaEventDisableTiming);
        cudaEventCreateWithFlags(&e1, cudaEventDisableTiming);
    }
    if (!attr_done) {
        cudaFuncSetAttribute(k_attn, cudaFuncAttributeMaxDynamicSharedMemorySize, ATTN_SMEM);
        cudaFuncSetAttribute(k_agg2, cudaFuncAttributeMaxDynamicSharedMemorySize, AGG_SMEM);
        cudaFuncSetAttribute(k_mm,   cudaFuncAttributeMaxDynamicSharedMemorySize, MM_SMEM);
        attr_done = true;
    }

    // fork attn onto s1
    cudaEventRecord(ef, 0);
    cudaStreamWaitEvent(s1, ef, 0);
    k_attn<<<2*BATCH, 128, ATTN_SMEM, s1>>>(M, Ws);

    // main chain: prep -> mm
    k_prep<<<PREP_B_BLOCKS + PREP_A_BLOCKS, 256>>>(bases, comp, root, x);
    k_mm<<<dim3(MROWS/128, JW/128), 256, MM_SMEM>>>(bias, out);

    // join attn before agg2
    cudaEventRecord(e1, s1);
    cudaStreamWaitEvent(0, e1, 0);
    k_agg2<<<2*BATCH, 256, AGG_SMEM>>>(esrc, edst, etyp, natt, out);
}

// round 17
// speedup vs baseline: 1.0839x; 1.0309x over previous
#include <cuda_runtime.h>
#include <cuda_fp16.h>
#include <cstdint>
#include <cstddef>

#define BATCH 64
#define T 90
#define O 5
#define D 256
#define H 256
#define EA 4096
#define R 5
#define NB 8
#define NPG 95
#define NTOT (BATCH*NPG)      /* 6080 */
#define JW 1536               /* 5*256 relation cols + 256 root cols */
#define XWC 1280              /* relation part of xW */
#define MROWS 6144            /* NTOT padded to 48*128 */
#define KP 256                /* single fp16 term */
#define KTILES 29             /* ceil(450/16) */

// ---------------- device scratch ----------------
__device__ __align__(128) __half g_xWh[(size_t)NTOT*XWC];         // 15.6 MB fp16
__device__ __align__(128) float g_P[(size_t)BATCH*T*T];           // softmax probs
__device__ __align__(128) __half g_Abf[(size_t)MROWS*KP];         // 3.1 MB  [row][k]
__device__ __align__(128) __half g_Bbf[(size_t)JW*KP];            // 0.8 MB  [n][k]

// ---------------- PTX helpers (baseline-PTX only: sm_80-class) ----------------
__device__ __forceinline__ uint32_t smem_u32(const void* p) {
    uint32_t a;
    asm("{ .reg .u64 t; cvta.to.shared.u64 t, %1; cvt.u32.u64 %0, t; }" : "=r"(a) : "l"(p));
    return a;
}
#define CP16(dst,src)    asm volatile("cp.async.cg.shared.global [%0], [%1], 16;"::"r"(dst),"l"(src):"memory")
#define CP_COMMIT()      asm volatile("cp.async.commit_group;":::"memory")
#define CP_WAIT(n)       asm volatile("cp.async.wait_group %0;"::"n"(n):"memory")
#define LDSM4(r0,r1,r2,r3,addr) \
    asm volatile("ldmatrix.sync.aligned.m8n8.x4.shared.b16 {%0,%1,%2,%3}, [%4];" \
                 : "=r"(r0),"=r"(r1),"=r"(r2),"=r"(r3) : "r"(addr))
#define LDSM4T(r0,r1,r2,r3,addr) \
    asm volatile("ldmatrix.sync.aligned.m8n8.x4.trans.shared.b16 {%0,%1,%2,%3}, [%4];" \
                 : "=r"(r0),"=r"(r1),"=r"(r2),"=r"(r3) : "r"(addr))
#define MMA16816(c, a, b0, b1) \
    asm volatile("mma.sync.aligned.m16n8k16.row.col.f32.f16.f16.f32 " \
                 "{%0,%1,%2,%3},{%4,%5,%6,%7},{%8,%9},{%0,%1,%2,%3};" \
                 : "+f"((c)[0]),"+f"((c)[1]),"+f"((c)[2]),"+f"((c)[3]) \
                 : "r"((a)[0]),"r"((a)[1]),"r"((a)[2]),"r"((a)[3]),"r"(b0),"r"(b1))

// ---------------- K1: prep = buildB + convA fused -------------------------
#define PREP_B_BLOCKS ((D*JW)/256)          /* 1536 */
#define PREP_A_BLOCKS ((MROWS*256)/256)     /* 6144 */
__global__ void k_prep(const float* __restrict__ bases,
                       const float* __restrict__ comp,
                       const float* __restrict__ root,
                       const float* __restrict__ x) {
    int bid = blockIdx.x, tid = threadIdx.x;
    if (bid < PREP_B_BLOCKS) {
        int idx = bid*256 + tid;
        int d = idx / JW, j = idx - d*JW;
        float v;
        if (j < XWC) {
            int r = j >> 8, h = j & 255;
            float s = 0.f;
            #pragma unroll
            for (int n = 0; n < NB; n++)
                s += comp[r*NB + n] * bases[((size_t)n*D + d)*H + h];
            v = s;
        } else {
            v = root[d*H + (j - XWC)];
        }
        g_Bbf[(size_t)j*KP + d] = __float2half(v);
    } else {
        int idx = (bid - PREP_B_BLOCKS)*256 + tid;
        int row = idx >> 8, col = idx & 255;
        float v = (row < NTOT) ? x[(size_t)row*D + col] : 0.f;
        g_Abf[(size_t)row*KP + col] = __float2half(v);
    }
}

// ---------------- K3: attention, 2 CTAs per graph (column halves) ---------
#define ATTN_SMEM ((96*257 + 48*257 + 90*49)*(int)sizeof(float))  /* 165672 */
__global__ void __launch_bounds__(128) k_attn(const float* __restrict__ M,
                                              const float* __restrict__ Ws) {
    extern __shared__ float sm[];
    float* sM = sm;                        // [96][257]
    float* sW = sm + 96*257;               // [48][257]
    float* sS = sm + 96*257 + 48*257;      // [90][49]
    int b = blockIdx.x >> 1;
    int sh = (blockIdx.x & 1) * 48;
    int tid = threadIdx.x;

    for (int q = tid; q < T*(D/4); q += 128) {
        int m = q >> 6, d4 = (q & 63) << 2;
        float4 v = *(const float4*)(M + ((size_t)b*T + m)*D + d4);
        float* p = sM + m*257 + d4;
        p[0]=v.x; p[1]=v.y; p[2]=v.z; p[3]=v.w;
    }
    for (int q = tid; q < 6*257; q += 128) sM[90*257 + q] = 0.f;
    for (int q = tid; q < 48*(D/4); q += 128) {
        int r = q >> 6, d4 = (q & 63) << 2;
        int s = sh + r;
        float4 v = make_float4(0.f,0.f,0.f,0.f);
        if (s < T) v = *(const float4*)(Ws + (size_t)s*D + d4);
        float* p = sW + r*257 + d4;
        p[0]=v.x; p[1]=v.y; p[2]=v.z; p[3]=v.w;
    }
    __syncthreads();

    int tx = tid & 7, ty = tid >> 3;
    int m0 = ty*6, s0 = tx*6;
    float acc[6][6];
    #pragma unroll
    for (int i = 0; i < 6; i++)
        #pragma unroll
        for (int j = 0; j < 6; j++) acc[i][j] = 0.f;
    for (int k = 0; k < D; k++) {
        float a[6], bb[6];
        #pragma unroll
        for (int i = 0; i < 6; i++) { a[i] = sM[(m0+i)*257 + k]; bb[i] = sW[(s0+i)*257 + k]; }
        #pragma unroll
        for (int i = 0; i < 6; i++)
            #pragma unroll
            for (int j = 0; j < 6; j++) acc[i][j] += a[i]*bb[j];
    }
    #pragma unroll
    for (int i = 0; i < 6; i++)
        #pragma unroll
        for (int j = 0; j < 6; j++) {
            int m = m0+i, sl = s0+j;
            if (m < T && sh + sl < T) sS[m*49 + sl] = acc[i][j];
        }
    __syncthreads();

    if (tid < 48 && sh + tid < T) {
        int sl = tid, sg = sh + tid;
        float mx = -1e30f;
        for (int t = 0; t < T; t++) mx = fmaxf(mx, sS[t*49 + sl]);
        float den = 0.f;
        for (int t = 0; t < T; t++) den += __expf(sS[t*49 + sl] - mx);
        float inv = 1.f/den;
        for (int t = 0; t < T; t++)
            g_P[((size_t)b*T + t)*T + sg] = __expf(sS[t*49 + sl] - mx) * inv;
    }
}

// ---------------- K2: mma.sync fp16 GEMM, 4-stage pipeline ----------------
#define SPITCH 40
#define STAGE_HALVES (128*SPITCH)
#define NKT (KP/32)          /* 8 */
#define NSTAGE 4
#define MM_SMEM (2*NSTAGE*STAGE_HALVES*2)   /* 81920 B */

__global__ void __launch_bounds__(256, 2) k_mm(const float* __restrict__ bias,
                                               float* __restrict__ out) {
    extern __shared__ __half smm[];
    uint32_t sbA = smem_u32(smm);
    uint32_t sbB = sbA + NSTAGE*STAGE_HALVES*2;
    int tid = threadIdx.x, lane = tid & 31, wid = tid >> 5;
    int warpM = wid & 3, warpN = wid >> 2;
    int row0 = blockIdx.x * 128;
    int colTile = blockIdx.y, col0 = colTile * 128;

    float c[2][8][4];
    #pragma unroll
    for (int mt = 0; mt < 2; mt++)
        #pragma unroll
        for (int nt = 0; nt < 8; nt++)
            #pragma unroll
            for (int q = 0; q < 4; q++) c[mt][nt][q] = 0.f;

    int lrow = tid >> 2, lseg = tid & 3;
    const __half* gA = g_Abf + (size_t)(row0 + lrow)*KP + lseg*8;
    const __half* gB = g_Bbf + (size_t)(col0 + lrow)*KP + lseg*8;
    uint32_t dA = sbA + (lrow*SPITCH + lseg*8)*2;
    uint32_t dB = sbB + (lrow*SPITCH + lseg*8)*2;
    const int rstep = 64;

    #pragma unroll
    for (int p = 0; p < NSTAGE-1; p++) {
        size_t go = (size_t)p*32;
        uint32_t soff = p * STAGE_HALVES * 2;
        CP16(dA + soff,                  (const char*)(gA + go));
        CP16(dA + soff + rstep*SPITCH*2, (const char*)(gA + go + (size_t)rstep*KP));
        CP16(dB + soff,                  (const char*)(gB + go));
        CP16(dB + soff + rstep*SPITCH*2, (const char*)(gB + go + (size_t)rstep*KP));
        CP_COMMIT();
    }

    int aRow = warpM*32 + ((lane>>3)&1)*8 + (lane&7);
    int aCol = ((lane>>4)&1)*8;
    int bRow = warpN*64 + ((lane>>4)&1)*8 + (lane&7);
    int bCol = ((lane>>3)&1)*8;
    uint32_t aAddr0 = sbA + (aRow*SPITCH + aCol)*2;
    uint32_t bAddr0 = sbB + (bRow*SPITCH + bCol)*2;

    #pragma unroll
    for (int kt = 0; kt < NKT; kt++) {
        if (kt <= NKT-3)      { CP_WAIT(2); }
        else if (kt == NKT-2) { CP_WAIT(1); }
        else                  { CP_WAIT(0); }
        __syncthreads();

        if (kt + NSTAGE - 1 < NKT) {
            size_t go = (size_t)(kt + NSTAGE - 1)*32;
            uint32_t soff = ((kt + NSTAGE - 1) & (NSTAGE-1)) * STAGE_HALVES * 2;
            CP16(dA + soff,                  (const char*)(gA + go));
            CP16(dA + soff + rstep*SPITCH*2, (const char*)(gA + go + (size_t)rstep*KP));
            CP16(dB + soff,                  (const char*)(gB + go));
            CP16(dB + soff + rstep*SPITCH*2, (const char*)(gB + go + (size_t)rstep*KP));
            CP_COMMIT();
        }

        uint32_t sa  = aAddr0 + (kt & (NSTAGE-1)) * STAGE_HALVES * 2;
        uint32_t sb2 = bAddr0 + (kt & (NSTAGE-1)) * STAGE_HALVES * 2;
        #pragma unroll
        for (int ks = 0; ks < 2; ks++) {
            uint32_t a[2][4];
            LDSM4(a[0][0],a[0][1],a[0][2],a[0][3], sa + ks*32);
            LDSM4(a[1][0],a[1][1],a[1][2],a[1][3], sa + ks*32 + 16*SPITCH*2);
            uint32_t b[8][2];
            #pragma unroll
            for (int ntp = 0; ntp < 4; ntp++) {
                uint32_t r0,r1,r2,r3;
                LDSM4(r0,r1,r2,r3, sb2 + ks*32 + ntp*16*SPITCH*2);
                b[ntp*2+0][0]=r0; b[ntp*2+0][1]=r1;
                b[ntp*2+1][0]=r2; b[ntp*2+1][1]=r3;
            }
            #pragma unroll
            for (int mt = 0; mt < 2; mt++)
                #pragma unroll
                for (int nt = 0; nt < 8; nt++)
                    MMA16816(c[mt][nt], a[mt], b[nt][0], b[nt][1]);
        }
    }

    int gr = lane >> 2, ci = lane & 3;
    #pragma unroll
    for (int mt = 0; mt < 2; mt++) {
        int r0w = row0 + warpM*32 + mt*16 + gr;
        #pragma unroll
        for (int nt = 0; nt < 8; nt++) {
            int col = col0 + warpN*64 + nt*8 + ci*2;
            if (colTile < 10) {
                if (r0w < NTOT)
                    *(__half2*)(g_xWh + (size_t)r0w*XWC + col) =
                        __floats2half2_rn(c[mt][nt][0], c[mt][nt][1]);
                if (r0w + 8 < NTOT)
                    *(__half2*)(g_xWh + (size_t)(r0w+8)*XWC + col) =
                        __floats2half2_rn(c[mt][nt][2], c[mt][nt][3]);
            } else {
                int h = col - XWC;
                float b0 = bias[h], b1 = bias[h+1];
                if (r0w < NTOT)
                    *(float2*)(out + (size_t)r0w*H + h) = make_float2(c[mt][nt][0] + b0, c[mt][nt][1] + b1);
                if (r0w + 8 < NTOT)
                    *(float2*)(out + (size_t)(r0w+8)*H + h) = make_float2(c[mt][nt][2] + b0, c[mt][nt][3] + b1);
            }
        }
    }
}

// ---------------- K5: fused edge GEMM, barrier-free per-warp B pipeline ---
#define CPITCH 472
#define WPITCH 48            /* per-warp B row pitch in BYTES (16-aligned) */
#define WSTG (16*WPITCH)     /* 768 B per warp per stage */
#define NBST 4
#define BSTG (8*WSTG)        /* 6144 B per stage */
#define AGG_SMEM (96*CPITCH*2 + NBST*BSTG + T*T*4) /* 90624+24576+32400 = 147600 */

__global__ void __launch_bounds__(256, 1) k_agg2(const int* __restrict__ edge_src,
                                                 const int* __restrict__ edge_dst,
                                                 const int* __restrict__ edge_type,
                                                 const float* __restrict__ node_att,
                                                 float* __restrict__ out) {
    extern __shared__ __half sm2[];
    __half* Cm = sm2;
    uint32_t sbC = smem_u32(Cm);
    uint32_t sbB = sbC + 96*CPITCH*2;
    float* sP = (float*)(sm2 + 96*CPITCH + (NBST*BSTG)/2);
    int b = blockIdx.x >> 1, nh = blockIdx.x & 1;
    int tid = threadIdx.x, lane = tid & 31, w = tid >> 5;
    int n0 = nh * 128;

    // per-lane B load slot: row = lane&15, chunk = lane>>4 (2 x 16B per row)
    int brow = lane & 15, bch = lane >> 4;
    uint32_t dBs = sbB + w*WSTG + brow*WPITCH + bch*16;
    // global src for ktile k, this warp's 16 n-cols
    // k index = kt*16 + brow; src=k/R, ty=k%R; col = n0 + w*16 + bch*8 halves

    // per-warp prologue: stages 0..2 (hidden under P-stage/zero/scatter)
    #pragma unroll
    for (int p = 0; p < NBST-1; p++) {
        int k = p*16 + brow;
        int src = k / R, ty = k - src*R;
        const __half* sp = g_xWh + ((size_t)(b*NPG + src)*XWC + ty*H + n0 + w*16) + bch*8;
        CP16(dBs + p*BSTG, (const char*)sp);
        CP_COMMIT();
    }

    // stage P[b] into smem (coalesced) and zero C
    const float4* gp = (const float4*)(g_P + (size_t)b*T*T);
    for (int i = tid; i < (T*T)/4; i += 256) ((float4*)sP)[i] = gp[i];
    uint4 z = make_uint4(0,0,0,0);
    for (int i = tid; i < 96*CPITCH/8; i += 256) ((uint4*)Cm)[i] = z;
    __syncthreads();

    // scatter attention edges: C[dst][src*R+ty] += P[dst][src]  (P from smem)
    #pragma unroll
    for (int q = 0; q < EA/256; q++) {
        int e = tid + q*256;
        int src = edge_src[(size_t)b*EA + e];
        int dst = edge_dst[(size_t)b*EA + e];
        int ty  = edge_type[(size_t)b*EA + e];
        atomicAdd(&Cm[dst*CPITCH + src*R + ty], __float2half(sP[dst*T + src]));
    }
    // tag entries (rows 90..94, unique)
    for (int q = tid; q < T*O; q += 256) {
        int src = q / O, o = q - src*O;
        Cm[(T+o)*CPITCH + src*R + (R-1)] = __float2half(node_att[((size_t)b*T + src)*O + o]);
    }
    __syncthreads();   // C complete & visible; last CTA-wide barrier

    float acc[6][2][4];
    #pragma unroll
    for (int mt = 0; mt < 6; mt++)
        #pragma unroll
        for (int nt = 0; nt < 2; nt++)
            #pragma unroll
            for (int q = 0; q < 4; q++) acc[mt][nt][q] = 0.f;

    uint32_t aAddr = sbC + ((((lane>>3)&1)*8 + (lane&7))*CPITCH + ((lane>>4)&1)*8)*2;
    // B fragment address inside this warp's region (row pitch WPITCH bytes)
    uint32_t bAddr = sbB + w*WSTG + (((lane>>3)&1)*8 + (lane&7))*WPITCH + ((lane>>4)&1)*16;

    // barrier-free mainloop: each warp waits only on its own cp.async groups
    for (int kt = 0; kt < KTILES; kt++) {
        if (kt < KTILES-2)       { CP_WAIT(2); }
        else if (kt == KTILES-2) { CP_WAIT(1); }
        else                     { CP_WAIT(0); }
        __syncwarp();

        if (kt + NBST - 1 < KTILES) {     // per-warp prefetch ktile kt+3
            int k = (kt + NBST - 1)*16 + brow;
            int src = k / R, ty = k - src*R;
            const __half* sp = g_xWh + ((size_t)(b*NPG + src)*XWC + ty*H + n0 + w*16) + bch*8;
            CP16(dBs + ((kt + NBST - 1) & (NBST-1))*BSTG, (const char*)sp);
        }
        CP_COMMIT();    // commit every iteration (possibly empty group) to keep counts uniform

        uint32_t bb0, bb1, bb2, bb3;
        LDSM4T(bb0, bb1, bb2, bb3, bAddr + (kt & (NBST-1))*BSTG);
        #pragma unroll
        for (int mt = 0; mt < 6; mt++) {
            uint32_t a[4];
            LDSM4(a[0], a[1], a[2], a[3], aAddr + mt*16*CPITCH*2 + kt*32);
            MMA16816(acc[mt][0], a, bb0, bb1);
            MMA16816(acc[mt][1], a, bb2, bb3);
        }
    }

    // epilogue: out[node] += acc  (warp-exclusive columns; no barrier needed)
    int gr = lane >> 2, ci = lane & 3;
    #pragma unroll
    for (int mt = 0; mt < 6; mt++) {
        #pragma unroll
        for (int hrow = 0; hrow < 2; hrow++) {
            int row = mt*16 + gr + hrow*8;
            if (row < NPG) {
                size_t node = (size_t)b*NPG + row;
                #pragma unroll
                for (int nt = 0; nt < 2; nt++) {
                    int col = n0 + w*16 + nt*8 + ci*2;
                    float2* p = (float2*)(out + node*H + col);
                    float2 v = *p;
                    v.x += acc[mt][nt][hrow*2 + 0];
                    v.y += acc[mt][nt][hrow*2 + 1];
                    *p = v;
                }
            }
        }
    }
}

// ---------------- launch (fork-join graph concurrency) --------------------
extern "C" void kernel_launch(void* const* d_in, const int* in_sizes, int n_in,
                              void* d_out, int out_size) {
    const float* M     = (const float*)d_in[0];
    const float* x     = (const float*)d_in[1];
    const float* natt  = (const float*)d_in[2];
    const float* Ws    = (const float*)d_in[3];
    const float* bases = (const float*)d_in[4];
    const float* comp  = (const float*)d_in[5];
    const float* root  = (const float*)d_in[6];
    const float* bias  = (const float*)d_in[7];
    const int* esrc    = (const int*)d_in[8];
    const int* edst    = (const int*)d_in[9];
    const int* etyp    = (const int*)d_in[10];
    float* out = (float*)d_out;

    static cudaStream_t s1 = nullptr;
    static cudaEvent_t  ef = nullptr, e1 = nullptr;
    static bool attr_done = false;
    if (!s1) {
        cudaStreamCreateWithFlags(&s1, cudaStreamNonBlocking);
        cudaEventCreateWithFlags(&ef, cudaEventDisableTiming);
        cudaEventCreateWithFlags(&e1, cudaEventDisableTiming);
    }
    if (!attr_done) {
        cudaFuncSetAttribute(k_attn, cudaFuncAttributeMaxDynamicSharedMemorySize, ATTN_SMEM);
        cudaFuncSetAttribute(k_agg2, cudaFuncAttributeMaxDynamicSharedMemorySize, AGG_SMEM);
        cudaFuncSetAttribute(k_mm,   cudaFuncAttributeMaxDynamicSharedMemorySize, MM_SMEM);
        attr_done = true;
    }

    // fork attn onto s1
    cudaEventRecord(ef, 0);
    cudaStreamWaitEvent(s1, ef, 0);
    k_attn<<<2*BATCH, 128, ATTN_SMEM, s1>>>(M, Ws);

    // main chain: prep -> mm
    k_prep<<<PREP_B_BLOCKS + PREP_A_BLOCKS, 256>>>(bases, comp, root, x);
    k_mm<<<dim3(MROWS/128, JW/128), 256, MM_SMEM>>>(bias, out);

    // join attn before agg2
    cudaEventRecord(e1, s1);
    cudaStreamWaitEvent(0, e1, 0);
    k_agg2<<<2*BATCH, 256, AGG_SMEM>>>(esrc, edst, etyp, natt, out);
}